// round 8
// baseline (speedup 1.0000x reference)
#include <cuda_runtime.h>
#include <cuda_bf16.h>
#include <math.h>

// Problem constants (fixed by the dataset problem)
#define NN    10000
#define EE    30000
#define INDIM 1024
#define H1N   4
#define C1N   512
#define D1N   2048   // H1*C1
#define H2N   8
#define C2N   460
#define D2N   3680   // H2*C2
#define E2N   40000  // EE + NN (self loops appended)

// ---------------- scratch (static device globals; no runtime allocation) ----
__device__ float g_Q [(size_t)NN * D1N];
__device__ float g_K [(size_t)NN * D1N];
__device__ float g_V [(size_t)NN * D1N];
__device__ float g_H [(size_t)NN * D1N];   // skip -> agg -> elu(h)
__device__ float g_GL[(size_t)NN * D2N];
__device__ float g_GR[(size_t)NN * D2N];

__device__ int   g_src[EE];
__device__ int   g_dst[EE];
__device__ int   g_is64;               // edge_index dtype flag (1 = int64)

__device__ float g_alpha1[EE * H1N];   // raw scores, then exp()
__device__ int   g_max1  [NN * H1N];
__device__ float g_sum1  [NN * H1N];

__device__ float g_a2  [E2N * H2N];    // raw scores, then exp()
__device__ int   g_max2[NN * H2N];
__device__ float g_sum2[NN * H2N];

// monotone int encoding of float for atomicMax
__device__ __forceinline__ int fenc(float f) {
    int i = __float_as_int(f);
    return (i >= 0) ? i : (i ^ 0x7fffffff);
}
__device__ __forceinline__ float fdec(int i) {
    return __int_as_float((i >= 0) ? i : (i ^ 0x7fffffff));
}

__device__ __forceinline__ float warp_sum(float v) {
    #pragma unroll
    for (int o = 16; o > 0; o >>= 1) v += __shfl_down_sync(0xffffffffu, v, o);
    return v;
}

// ---------------- edge-index dtype detection + unpack -----------------------
// If the buffer holds int64 values (all < 2^31), every odd 32-bit word (the
// high half) is zero. If it holds int32 [s,d,s,d,...], odd words are random
// dst indices in [0,10000) — 64 consecutive zeros is impossible in practice.
// Reads only the first 512 bytes: in-bounds for either dtype.
__global__ void detect_idx_kernel(const int* __restrict__ w) {
    int all0 = 1;
    #pragma unroll
    for (int i = 1; i < 128; i += 2)
        if (w[i] != 0) { all0 = 0; break; }
    g_is64 = all0;
}

// Unpack edge_index into int arrays (bounds match the ACTUAL dtype).
__global__ void unpack_idx_kernel(const void* __restrict__ ei) {
    int e = blockIdx.x * blockDim.x + threadIdx.x;
    if (e >= EE) return;
    if (g_is64) {
        const long long* p = (const long long*)ei;
        g_src[e] = (int)p[2 * e];
        g_dst[e] = (int)p[2 * e + 1];
    } else {
        const int* p = (const int*)ei;
        g_src[e] = p[2 * e];
        g_dst[e] = p[2 * e + 1];
    }
}

// ---------------- init ------------------------------------------------------
__global__ void init_stats_kernel() {
    int i = blockIdx.x * blockDim.x + threadIdx.x;
    if (i < NN * H1N) { g_max1[i] = (int)0x80000000; g_sum1[i] = 0.f; }
    if (i < NN * H2N) { g_max2[i] = (int)0x80000000; g_sum2[i] = 0.f; }
}

__global__ void out_init_kernel(const float* __restrict__ b_out, float* __restrict__ out) {
    int i = blockIdx.x * blockDim.x + threadIdx.x;
    if (i < NN * C2N) out[i] = __ldg(&b_out[i % C2N]);
}

// ---------------- SGEMM: C = A(MxK) @ B(KxN) + bias(N) ----------------------
// 128x128 tile, BK=8, 256 threads, 8x8 micro-tile.
// Two-stage smem double buffering + register prefetch: ONE barrier per K-slice.
__global__ __launch_bounds__(256, 2) void sgemm_bias(
    int M, int N, int K,
    const float* __restrict__ A,
    const float* __restrict__ B,
    const float* __restrict__ bias,
    float* __restrict__ C)
{
    __shared__ float As[2][8][128];
    __shared__ float Bs[2][8][132];   // pad to dodge store-phase conflicts

    const int tid = threadIdx.x;
    const int blockRow = blockIdx.y * 128;
    const int blockCol = blockIdx.x * 128;

    const int tr = (tid / 16) * 8;
    const int tc = (tid % 16) * 8;

    const int aRow = tid >> 1;          // 0..127
    const int aCol = (tid & 1) * 4;     // 0 or 4
    const int bRow = tid >> 5;          // 0..7
    const int bCol = (tid & 31) * 4;    // 0..124

    float acc[8][8] = {};

    const int gr = blockRow + aRow;
    const int gc = blockCol + bCol;
    const bool aOK = (gr < M);
    const bool bFull = (gc + 3 < N);

    const float* Abase = A + (size_t)gr * K + aCol;      // deref only if aOK
    const float* Bbase = B + (size_t)bRow * N + gc;

    // ---- load slice 0 into registers ----
    float4 av = make_float4(0.f, 0.f, 0.f, 0.f), bv4;
    if (aOK) av = *reinterpret_cast<const float4*>(Abase);
    if (bFull) {
        bv4 = *reinterpret_cast<const float4*>(Bbase);
    } else {
        bv4.x = (gc + 0 < N) ? Bbase[0] : 0.f;
        bv4.y = (gc + 1 < N) ? Bbase[1] : 0.f;
        bv4.z = (gc + 2 < N) ? Bbase[2] : 0.f;
        bv4.w = (gc + 3 < N) ? Bbase[3] : 0.f;
    }

    // ---- store slice 0 into buffer 0 ----
    As[0][aCol + 0][aRow] = av.x;
    As[0][aCol + 1][aRow] = av.y;
    As[0][aCol + 2][aRow] = av.z;
    As[0][aCol + 3][aRow] = av.w;
    Bs[0][bRow][bCol + 0] = bv4.x;
    Bs[0][bRow][bCol + 1] = bv4.y;
    Bs[0][bRow][bCol + 2] = bv4.z;
    Bs[0][bRow][bCol + 3] = bv4.w;
    __syncthreads();

    int buf = 0;
    for (int k0 = 0; k0 < K; k0 += 8) {
        const int kn = k0 + 8;

        // ---- prefetch next slice into registers (overlaps with FFMAs) ----
        if (kn < K) {
            av = make_float4(0.f, 0.f, 0.f, 0.f);
            if (aOK) av = *reinterpret_cast<const float4*>(Abase + kn);
            const float* bp = Bbase + (size_t)kn * N;
            if (bFull) {
                bv4 = *reinterpret_cast<const float4*>(bp);
            } else {
                bv4.x = (gc + 0 < N) ? bp[0] : 0.f;
                bv4.y = (gc + 1 < N) ? bp[1] : 0.f;
                bv4.z = (gc + 2 < N) ? bp[2] : 0.f;
                bv4.w = (gc + 3 < N) ? bp[3] : 0.f;
            }
        }

        // ---- compute on current buffer ----
        #pragma unroll
        for (int kk = 0; kk < 8; kk++) {
            float4 a0 = *reinterpret_cast<const float4*>(&As[buf][kk][tr]);
            float4 a1 = *reinterpret_cast<const float4*>(&As[buf][kk][tr + 4]);
            float4 b0 = *reinterpret_cast<const float4*>(&Bs[buf][kk][tc]);
            float4 b1 = *reinterpret_cast<const float4*>(&Bs[buf][kk][tc + 4]);
            float ra[8] = {a0.x, a0.y, a0.z, a0.w, a1.x, a1.y, a1.z, a1.w};
            float rb[8] = {b0.x, b0.y, b0.z, b0.w, b1.x, b1.y, b1.z, b1.w};
            #pragma unroll
            for (int i = 0; i < 8; i++)
                #pragma unroll
                for (int j = 0; j < 8; j++)
                    acc[i][j] += ra[i] * rb[j];
        }

        // ---- store prefetched slice into the other buffer ----
        if (kn < K) {
            int nb = buf ^ 1;
            As[nb][aCol + 0][aRow] = av.x;
            As[nb][aCol + 1][aRow] = av.y;
            As[nb][aCol + 2][aRow] = av.z;
            As[nb][aCol + 3][aRow] = av.w;
            Bs[nb][bRow][bCol + 0] = bv4.x;
            Bs[nb][bRow][bCol + 1] = bv4.y;
            Bs[nb][bRow][bCol + 2] = bv4.z;
            Bs[nb][bRow][bCol + 3] = bv4.w;
            __syncthreads();          // one barrier per slice
            buf = nb;
        }
    }

    float bb[8];
    #pragma unroll
    for (int j = 0; j < 8; j++) {
        int c = blockCol + tc + j;
        bb[j] = (c < N) ? __ldg(&bias[c]) : 0.f;
    }
    #pragma unroll
    for (int i = 0; i < 8; i++) {
        int r = blockRow + tr + i;
        if (r >= M) continue;
        #pragma unroll
        for (int j = 0; j < 8; j++) {
            int c = blockCol + tc + j;
            if (c < N) C[(size_t)r * N + c] = acc[i][j] + bb[j];
        }
    }
}

// ---------------- layer 1 edge ops ------------------------------------------
// one block per edge; 4 warps = 4 heads
__global__ void edge_alpha1_kernel() {
    int e = blockIdx.x;
    int h = threadIdx.x >> 5;
    int lane = threadIdx.x & 31;
    int s = g_src[e];
    int d = g_dst[e];
    const float4* qp = (const float4*)(g_Q + (size_t)d * D1N + h * C1N);
    const float4* kp = (const float4*)(g_K + (size_t)s * D1N + h * C1N);
    float acc = 0.f;
    #pragma unroll
    for (int c = lane; c < C1N / 4; c += 32) {
        float4 q4 = qp[c], k4 = kp[c];
        acc += q4.x * k4.x + q4.y * k4.y + q4.z * k4.z + q4.w * k4.w;
    }
    acc = warp_sum(acc);
    if (lane == 0) {
        float val = acc * 0.044194173824159216f;  // 1/sqrt(512)
        g_alpha1[e * H1N + h] = val;
        atomicMax(&g_max1[d * H1N + h], fenc(val));
    }
}

__global__ void exp1_kernel() {
    int idx = blockIdx.x * blockDim.x + threadIdx.x;
    if (idx >= EE * H1N) return;
    int e = idx / H1N;
    int h = idx - e * H1N;
    int d = g_dst[e];
    float m  = fdec(g_max1[d * H1N + h]);
    float ex = expf(g_alpha1[idx] - m);
    g_alpha1[idx] = ex;
    atomicAdd(&g_sum1[d * H1N + h], ex);
}

// one block (256 thr) per edge: agg[d] += v[s] * softmax_weight (float4 loads)
__global__ void agg1_kernel() {
    int e = blockIdx.x;
    int s = g_src[e];
    int d = g_dst[e];
    __shared__ float w[H1N];
    if (threadIdx.x < H1N)
        w[threadIdx.x] = g_alpha1[e * H1N + threadIdx.x] /
                         (g_sum1[d * H1N + threadIdx.x] + 1e-16f);
    __syncthreads();
    const float4* vp = (const float4*)(g_V + (size_t)s * D1N);
    float* ap = g_H + (size_t)d * D1N;
    // D1N/4 = 512 float4s; head of float4 j is (4j)>>9 = j>>7
    for (int j = threadIdx.x; j < D1N / 4; j += 256) {
        float4 v4 = vp[j];
        float wt = w[j >> 7];
        int base = j * 4;
        atomicAdd(&ap[base + 0], v4.x * wt);
        atomicAdd(&ap[base + 1], v4.y * wt);
        atomicAdd(&ap[base + 2], v4.z * wt);
        atomicAdd(&ap[base + 3], v4.w * wt);
    }
}

__global__ void elu_kernel() {
    int i = blockIdx.x * blockDim.x + threadIdx.x;
    if (i < (NN * D1N) / 4) {
        float4* p = (float4*)g_H;
        float4 v = p[i];
        v.x = (v.x > 0.f) ? v.x : expm1f(v.x);
        v.y = (v.y > 0.f) ? v.y : expm1f(v.y);
        v.z = (v.z > 0.f) ? v.z : expm1f(v.z);
        v.w = (v.w > 0.f) ? v.w : expm1f(v.w);
        p[i] = v;
    }
}

// ---------------- layer 2 edge ops ------------------------------------------
// one block per edge2; 8 warps = 8 heads
__global__ void edge_a2_kernel(const float* __restrict__ att) {
    int e = blockIdx.x;
    int h = threadIdx.x >> 5;
    int lane = threadIdx.x & 31;
    int s, d;
    if (e < EE) { s = g_src[e]; d = g_dst[e]; }
    else        { s = e - EE; d = e - EE; }
    const float* glp = g_GL + (size_t)s * D2N + h * C2N;
    const float* grp = g_GR + (size_t)d * D2N + h * C2N;
    const float* ap  = att + h * C2N;
    float acc = 0.f;
    for (int c = lane; c < C2N; c += 32) {
        float v = glp[c] + grp[c];
        v = (v > 0.f) ? v : 0.2f * v;           // leaky_relu(0.2)
        acc += v * __ldg(&ap[c]);
    }
    acc = warp_sum(acc);
    if (lane == 0) {
        g_a2[e * H2N + h] = acc;
        atomicMax(&g_max2[d * H2N + h], fenc(acc));
    }
}

__global__ void exp2_kernel() {
    int idx = blockIdx.x * blockDim.x + threadIdx.x;
    if (idx >= E2N * H2N) return;
    int e = idx / H2N;
    int h = idx - e * H2N;
    int d = (e < EE) ? g_dst[e] : (e - EE);
    float m  = fdec(g_max2[d * H2N + h]);
    float ex = expf(g_a2[idx] - m);
    g_a2[idx] = ex;
    atomicAdd(&g_sum2[d * H2N + h], ex);
}

// one block per edge2: out[d, c] += (1/H2) * sum_h gl[s,h,c] * w[h]
__global__ void out_acc_kernel(float* __restrict__ out) {
    int e = blockIdx.x;
    int s, d;
    if (e < EE) { s = g_src[e]; d = g_dst[e]; }
    else        { s = e - EE; d = e - EE; }
    __shared__ float w[H2N];
    if (threadIdx.x < H2N)
        w[threadIdx.x] = g_a2[e * H2N + threadIdx.x] /
                         (g_sum2[d * H2N + threadIdx.x] + 1e-16f) * 0.125f;
    __syncthreads();
    const float* glp = g_GL + (size_t)s * D2N;
    float* op = out + (size_t)d * C2N;
    for (int c = threadIdx.x; c < C2N; c += 256) {
        float acc = 0.f;
        #pragma unroll
        for (int h = 0; h < H2N; h++)
            acc += __ldg(&glp[h * C2N + c]) * w[h];
        atomicAdd(&op[c], acc);
    }
}

// ---------------- host ------------------------------------------------------
extern "C" void kernel_launch(void* const* d_in, const int* in_sizes, int n_in,
                              void* d_out, int out_size) {
    const float* x     = (const float*)d_in[0];
    const void*  ei    = d_in[1];               // dtype detected on device
    const float* Wq    = (const float*)d_in[2];
    const float* bq    = (const float*)d_in[3];
    const float* Wk    = (const float*)d_in[4];
    const float* bk    = (const float*)d_in[5];
    const float* Wv    = (const float*)d_in[6];
    const float* bv    = (const float*)d_in[7];
    const float* Wsk   = (const float*)d_in[8];
    const float* bsk   = (const float*)d_in[9];
    const float* Wl    = (const float*)d_in[10];
    const float* bl    = (const float*)d_in[11];
    const float* Wr    = (const float*)d_in[12];
    const float* br    = (const float*)d_in[13];
    const float* att   = (const float*)d_in[14];
    const float* b_out = (const float*)d_in[15];
    float*       out   = (float*)d_out;

    // Resolve scratch addresses ONCE (first call happens outside graph
    // capture; replays then contain only kernel launches).
    static float *pQ = nullptr, *pK = nullptr, *pV = nullptr,
                 *pH = nullptr, *pGL = nullptr, *pGR = nullptr;
    if (!pQ) {
        void* p;
        cudaGetSymbolAddress(&p, g_Q);  pQ  = (float*)p;
        cudaGetSymbolAddress(&p, g_K);  pK  = (float*)p;
        cudaGetSymbolAddress(&p, g_V);  pV  = (float*)p;
        cudaGetSymbolAddress(&p, g_H);  pH  = (float*)p;
        cudaGetSymbolAddress(&p, g_GL); pGL = (float*)p;
        cudaGetSymbolAddress(&p, g_GR); pGR = (float*)p;
    }

    // edge-index dtype detection + unpack (reads stay in-bounds either way)
    detect_idx_kernel<<<1, 1>>>((const int*)ei);
    unpack_idx_kernel<<<(EE + 255) / 256, 256>>>(ei);

    // reset softmax stats + output
    init_stats_kernel<<<(NN * H2N + 255) / 256, 256>>>();
    out_init_kernel<<<(NN * C2N + 255) / 256, 256>>>(b_out, out);

    // layer-1 projections: M=10000, K=1024, N=2048
    dim3 g1(D1N / 128, (NN + 127) / 128);
    sgemm_bias<<<g1, 256>>>(NN, D1N, INDIM, x, Wq,  bq,  pQ);
    sgemm_bias<<<g1, 256>>>(NN, D1N, INDIM, x, Wk,  bk,  pK);
    sgemm_bias<<<g1, 256>>>(NN, D1N, INDIM, x, Wv,  bv,  pV);
    sgemm_bias<<<g1, 256>>>(NN, D1N, INDIM, x, Wsk, bsk, pH);  // skip into agg buffer

    // layer-1 attention + aggregation
    edge_alpha1_kernel<<<EE, H1N * 32>>>();
    exp1_kernel<<<(EE * H1N + 255) / 256, 256>>>();
    agg1_kernel<<<EE, 256>>>();
    elu_kernel<<<((NN * D1N) / 4 + 255) / 256, 256>>>();

    // layer-2 projections: M=10000, K=2048, N=3680
    dim3 g2((D2N + 127) / 128, (NN + 127) / 128);
    sgemm_bias<<<g2, 256>>>(NN, D2N, D1N, pH, Wl, bl, pGL);
    sgemm_bias<<<g2, 256>>>(NN, D2N, D1N, pH, Wr, br, pGR);

    // layer-2 attention + output
    edge_a2_kernel<<<E2N, H2N * 32>>>(att);
    exp2_kernel<<<(E2N * H2N + 255) / 256, 256>>>();
    out_acc_kernel<<<E2N, 256>>>(out);
}

// round 11
// speedup vs baseline: 2.4548x; 2.4548x over previous
#include <cuda_runtime.h>
#include <cuda_bf16.h>
#include <math.h>
#include <stdint.h>

// Problem constants (fixed by the dataset problem)
#define NN    10000
#define EE    30000
#define INDIM 1024
#define H1N   4
#define C1N   512
#define D1N   2048   // H1*C1
#define H2N   8
#define C2N   460
#define D2N   3680   // H2*C2
#define E2N   40000  // EE + NN (self loops appended)

// ---------------- scratch (static device globals; no runtime allocation) ----
__device__ float g_Q [(size_t)NN * D1N];
__device__ float g_K [(size_t)NN * D1N];
__device__ float g_V [(size_t)NN * D1N];
__device__ float g_H [(size_t)NN * D1N];   // skip -> agg -> elu(h)
__device__ float g_GL[(size_t)NN * D2N];
__device__ float g_GR[(size_t)NN * D2N];

__device__ int   g_src[EE];
__device__ int   g_dst[EE];
__device__ int   g_is64;               // edge_index dtype flag (1 = int64)

__device__ float g_alpha1[EE * H1N];   // raw scores, then exp()
__device__ int   g_max1  [NN * H1N];
__device__ float g_sum1  [NN * H1N];

__device__ float g_a2  [E2N * H2N];    // raw scores, then exp()
__device__ int   g_max2[NN * H2N];
__device__ float g_sum2[NN * H2N];

// monotone int encoding of float for atomicMax
__device__ __forceinline__ int fenc(float f) {
    int i = __float_as_int(f);
    return (i >= 0) ? i : (i ^ 0x7fffffff);
}
__device__ __forceinline__ float fdec(int i) {
    return __int_as_float((i >= 0) ? i : (i ^ 0x7fffffff));
}

__device__ __forceinline__ float warp_sum(float v) {
    #pragma unroll
    for (int o = 16; o > 0; o >>= 1) v += __shfl_down_sync(0xffffffffu, v, o);
    return v;
}

// float -> tf32 bits (round to nearest)
__device__ __forceinline__ uint32_t f2tf32(float f) {
    uint32_t r;
    asm("cvt.rna.tf32.f32 %0, %1;" : "=r"(r) : "f"(f));
    return r;
}

// ---------------- edge-index dtype detection + unpack -----------------------
__global__ void detect_idx_kernel(const int* __restrict__ w) {
    int all0 = 1;
    #pragma unroll
    for (int i = 1; i < 128; i += 2)
        if (w[i] != 0) { all0 = 0; break; }
    g_is64 = all0;
}

__global__ void unpack_idx_kernel(const void* __restrict__ ei) {
    int e = blockIdx.x * blockDim.x + threadIdx.x;
    if (e >= EE) return;
    if (g_is64) {
        const long long* p = (const long long*)ei;
        g_src[e] = (int)p[2 * e];
        g_dst[e] = (int)p[2 * e + 1];
    } else {
        const int* p = (const int*)ei;
        g_src[e] = p[2 * e];
        g_dst[e] = p[2 * e + 1];
    }
}

// ---------------- init ------------------------------------------------------
__global__ void init_stats_kernel() {
    int i = blockIdx.x * blockDim.x + threadIdx.x;
    if (i < NN * H1N) { g_max1[i] = (int)0x80000000; g_sum1[i] = 0.f; }
    if (i < NN * H2N) { g_max2[i] = (int)0x80000000; g_sum2[i] = 0.f; }
}

__global__ void out_init_kernel(const float* __restrict__ b_out, float* __restrict__ out) {
    int i = blockIdx.x * blockDim.x + threadIdx.x;
    if (i < NN * C2N) out[i] = __ldg(&b_out[i % C2N]);
}

// ---------------- TF32 tensor-core GEMM: C = A(MxK) @ B(KxN) + bias(N) ------
// 128x128 CTA tile, BK=8, 256 threads = 8 warps (2 M x 4 N), warp tile 64x32,
// mma.sync.m16n8k8.tf32. Smem stride 136 words => conflict-free fragment LDS.
// Double-buffered smem + register prefetch: one barrier per K-slice.
__global__ __launch_bounds__(256, 2) void sgemm_tf32(
    int M, int N, int K,
    const float* __restrict__ A,
    const float* __restrict__ B,
    const float* __restrict__ bias,
    float* __restrict__ C)
{
    __shared__ uint32_t As[2][8][136];   // [buf][k][row]
    __shared__ uint32_t Bs[2][8][136];   // [buf][k][col]

    const int tid  = threadIdx.x;
    const int wid  = tid >> 5;
    const int lane = tid & 31;
    const int gid  = lane >> 2;          // 0..7
    const int tig  = lane & 3;           // 0..3
    const int warpM = wid >> 2;          // 0..1
    const int warpN = wid & 3;           // 0..3

    const int blockRow = blockIdx.y * 128;
    const int blockCol = blockIdx.x * 128;

    // global-load roles (same mapping as the fp32 version)
    const int aRow = tid >> 1;           // 0..127
    const int aCol = (tid & 1) * 4;      // 0 or 4
    const int bRow = tid >> 5;           // 0..7
    const int bCol = (tid & 31) * 4;     // 0..124

    const int gr = blockRow + aRow;
    const int gc = blockCol + bCol;
    const bool aOK = (gr < M);
    const bool bFull = (gc + 3 < N);

    const float* Abase = A + (size_t)gr * K + aCol;   // deref only if aOK
    const float* Bbase = B + (size_t)bRow * N + gc;

    float acc[4][4][4];
    #pragma unroll
    for (int mt = 0; mt < 4; mt++)
        #pragma unroll
        for (int nt = 0; nt < 4; nt++)
            #pragma unroll
            for (int i = 0; i < 4; i++) acc[mt][nt][i] = 0.f;

    // ---- load slice 0 into registers ----
    float4 av = make_float4(0.f, 0.f, 0.f, 0.f), bv4;
    if (aOK) av = *reinterpret_cast<const float4*>(Abase);
    if (bFull) {
        bv4 = *reinterpret_cast<const float4*>(Bbase);
    } else {
        bv4.x = (gc + 0 < N) ? Bbase[0] : 0.f;
        bv4.y = (gc + 1 < N) ? Bbase[1] : 0.f;
        bv4.z = (gc + 2 < N) ? Bbase[2] : 0.f;
        bv4.w = (gc + 3 < N) ? Bbase[3] : 0.f;
    }

    // ---- store slice 0 (tf32-converted) into buffer 0 ----
    As[0][aCol + 0][aRow] = f2tf32(av.x);
    As[0][aCol + 1][aRow] = f2tf32(av.y);
    As[0][aCol + 2][aRow] = f2tf32(av.z);
    As[0][aCol + 3][aRow] = f2tf32(av.w);
    Bs[0][bRow][bCol + 0] = f2tf32(bv4.x);
    Bs[0][bRow][bCol + 1] = f2tf32(bv4.y);
    Bs[0][bRow][bCol + 2] = f2tf32(bv4.z);
    Bs[0][bRow][bCol + 3] = f2tf32(bv4.w);
    __syncthreads();

    const int rA = warpM * 64 + gid;     // + mt*16 (+8)
    const int cB = warpN * 32 + gid;     // + nt*8

    int buf = 0;
    for (int k0 = 0; k0 < K; k0 += 8) {
        const int kn = k0 + 8;

        // ---- prefetch next slice into registers ----
        if (kn < K) {
            av = make_float4(0.f, 0.f, 0.f, 0.f);
            if (aOK) av = *reinterpret_cast<const float4*>(Abase + kn);
            const float* bp = Bbase + (size_t)kn * N;
            if (bFull) {
                bv4 = *reinterpret_cast<const float4*>(bp);
            } else {
                bv4.x = (gc + 0 < N) ? bp[0] : 0.f;
                bv4.y = (gc + 1 < N) ? bp[1] : 0.f;
                bv4.z = (gc + 2 < N) ? bp[2] : 0.f;
                bv4.w = (gc + 3 < N) ? bp[3] : 0.f;
            }
        }

        // ---- fragments from current buffer ----
        uint32_t afr[4][4];   // [mt][a0..a3]
        uint32_t bfr[4][2];   // [nt][b0..b1]
        #pragma unroll
        for (int mt = 0; mt < 4; mt++) {
            int r = rA + mt * 16;
            afr[mt][0] = As[buf][tig    ][r];
            afr[mt][1] = As[buf][tig    ][r + 8];
            afr[mt][2] = As[buf][tig + 4][r];
            afr[mt][3] = As[buf][tig + 4][r + 8];
        }
        #pragma unroll
        for (int nt = 0; nt < 4; nt++) {
            int c = cB + nt * 8;
            bfr[nt][0] = Bs[buf][tig    ][c];
            bfr[nt][1] = Bs[buf][tig + 4][c];
        }

        // ---- 16 mma per warp per k-slice ----
        #pragma unroll
        for (int mt = 0; mt < 4; mt++)
            #pragma unroll
            for (int nt = 0; nt < 4; nt++) {
                asm volatile(
                    "mma.sync.aligned.m16n8k8.row.col.f32.tf32.tf32.f32 "
                    "{%0,%1,%2,%3}, {%4,%5,%6,%7}, {%8,%9}, {%0,%1,%2,%3};\n"
                    : "+f"(acc[mt][nt][0]), "+f"(acc[mt][nt][1]),
                      "+f"(acc[mt][nt][2]), "+f"(acc[mt][nt][3])
                    : "r"(afr[mt][0]), "r"(afr[mt][1]),
                      "r"(afr[mt][2]), "r"(afr[mt][3]),
                      "r"(bfr[nt][0]), "r"(bfr[nt][1]));
            }

        // ---- store prefetched slice into the other buffer ----
        if (kn < K) {
            int nb = buf ^ 1;
            As[nb][aCol + 0][aRow] = f2tf32(av.x);
            As[nb][aCol + 1][aRow] = f2tf32(av.y);
            As[nb][aCol + 2][aRow] = f2tf32(av.z);
            As[nb][aCol + 3][aRow] = f2tf32(av.w);
            Bs[nb][bRow][bCol + 0] = f2tf32(bv4.x);
            Bs[nb][bRow][bCol + 1] = f2tf32(bv4.y);
            Bs[nb][bRow][bCol + 2] = f2tf32(bv4.z);
            Bs[nb][bRow][bCol + 3] = f2tf32(bv4.w);
            __syncthreads();
            buf = nb;
        }
    }

    // ---- epilogue: bias + guarded stores ----
    // c0,c1 -> (row0, col, col+1); c2,c3 -> (row0+8, col, col+1)
    #pragma unroll
    for (int mt = 0; mt < 4; mt++) {
        int r0 = blockRow + warpM * 64 + mt * 16 + gid;
        #pragma unroll
        for (int nt = 0; nt < 4; nt++) {
            int c0 = blockCol + warpN * 32 + nt * 8 + tig * 2;
            float bb0 = (c0     < N) ? __ldg(&bias[c0])     : 0.f;
            float bb1 = (c0 + 1 < N) ? __ldg(&bias[c0 + 1]) : 0.f;
            if (r0 < M) {
                if (c0     < N) C[(size_t)r0 * N + c0]     = acc[mt][nt][0] + bb0;
                if (c0 + 1 < N) C[(size_t)r0 * N + c0 + 1] = acc[mt][nt][1] + bb1;
            }
            if (r0 + 8 < M) {
                if (c0     < N) C[(size_t)(r0 + 8) * N + c0]     = acc[mt][nt][2] + bb0;
                if (c0 + 1 < N) C[(size_t)(r0 + 8) * N + c0 + 1] = acc[mt][nt][3] + bb1;
            }
        }
    }
}

// ---------------- layer 1 edge ops ------------------------------------------
__global__ void edge_alpha1_kernel() {
    int e = blockIdx.x;
    int h = threadIdx.x >> 5;
    int lane = threadIdx.x & 31;
    int s = g_src[e];
    int d = g_dst[e];
    const float4* qp = (const float4*)(g_Q + (size_t)d * D1N + h * C1N);
    const float4* kp = (const float4*)(g_K + (size_t)s * D1N + h * C1N);
    float acc = 0.f;
    #pragma unroll
    for (int c = lane; c < C1N / 4; c += 32) {
        float4 q4 = qp[c], k4 = kp[c];
        acc += q4.x * k4.x + q4.y * k4.y + q4.z * k4.z + q4.w * k4.w;
    }
    acc = warp_sum(acc);
    if (lane == 0) {
        float val = acc * 0.044194173824159216f;  // 1/sqrt(512)
        g_alpha1[e * H1N + h] = val;
        atomicMax(&g_max1[d * H1N + h], fenc(val));
    }
}

__global__ void exp1_kernel() {
    int idx = blockIdx.x * blockDim.x + threadIdx.x;
    if (idx >= EE * H1N) return;
    int e = idx / H1N;
    int h = idx - e * H1N;
    int d = g_dst[e];
    float m  = fdec(g_max1[d * H1N + h]);
    float ex = expf(g_alpha1[idx] - m);
    g_alpha1[idx] = ex;
    atomicAdd(&g_sum1[d * H1N + h], ex);
}

__global__ void agg1_kernel() {
    int e = blockIdx.x;
    int s = g_src[e];
    int d = g_dst[e];
    __shared__ float w[H1N];
    if (threadIdx.x < H1N)
        w[threadIdx.x] = g_alpha1[e * H1N + threadIdx.x] /
                         (g_sum1[d * H1N + threadIdx.x] + 1e-16f);
    __syncthreads();
    const float4* vp = (const float4*)(g_V + (size_t)s * D1N);
    float* ap = g_H + (size_t)d * D1N;
    for (int j = threadIdx.x; j < D1N / 4; j += 256) {
        float4 v4 = vp[j];
        float wt = w[j >> 7];
        int base = j * 4;
        atomicAdd(&ap[base + 0], v4.x * wt);
        atomicAdd(&ap[base + 1], v4.y * wt);
        atomicAdd(&ap[base + 2], v4.z * wt);
        atomicAdd(&ap[base + 3], v4.w * wt);
    }
}

__global__ void elu_kernel() {
    int i = blockIdx.x * blockDim.x + threadIdx.x;
    if (i < (NN * D1N) / 4) {
        float4* p = (float4*)g_H;
        float4 v = p[i];
        v.x = (v.x > 0.f) ? v.x : expm1f(v.x);
        v.y = (v.y > 0.f) ? v.y : expm1f(v.y);
        v.z = (v.z > 0.f) ? v.z : expm1f(v.z);
        v.w = (v.w > 0.f) ? v.w : expm1f(v.w);
        p[i] = v;
    }
}

// ---------------- layer 2 edge ops ------------------------------------------
__global__ void edge_a2_kernel(const float* __restrict__ att) {
    int e = blockIdx.x;
    int h = threadIdx.x >> 5;
    int lane = threadIdx.x & 31;
    int s, d;
    if (e < EE) { s = g_src[e]; d = g_dst[e]; }
    else        { s = e - EE; d = e - EE; }
    const float* glp = g_GL + (size_t)s * D2N + h * C2N;
    const float* grp = g_GR + (size_t)d * D2N + h * C2N;
    const float* ap  = att + h * C2N;
    float acc = 0.f;
    for (int c = lane; c < C2N; c += 32) {
        float v = glp[c] + grp[c];
        v = (v > 0.f) ? v : 0.2f * v;           // leaky_relu(0.2)
        acc += v * __ldg(&ap[c]);
    }
    acc = warp_sum(acc);
    if (lane == 0) {
        g_a2[e * H2N + h] = acc;
        atomicMax(&g_max2[d * H2N + h], fenc(acc));
    }
}

__global__ void exp2_kernel() {
    int idx = blockIdx.x * blockDim.x + threadIdx.x;
    if (idx >= E2N * H2N) return;
    int e = idx / H2N;
    int h = idx - e * H2N;
    int d = (e < EE) ? g_dst[e] : (e - EE);
    float m  = fdec(g_max2[d * H2N + h]);
    float ex = expf(g_a2[idx] - m);
    g_a2[idx] = ex;
    atomicAdd(&g_sum2[d * H2N + h], ex);
}

__global__ void out_acc_kernel(float* __restrict__ out) {
    int e = blockIdx.x;
    int s, d;
    if (e < EE) { s = g_src[e]; d = g_dst[e]; }
    else        { s = e - EE; d = e - EE; }
    __shared__ float w[H2N];
    if (threadIdx.x < H2N)
        w[threadIdx.x] = g_a2[e * H2N + threadIdx.x] /
                         (g_sum2[d * H2N + threadIdx.x] + 1e-16f) * 0.125f;
    __syncthreads();
    const float* glp = g_GL + (size_t)s * D2N;
    float* op = out + (size_t)d * C2N;
    for (int c = threadIdx.x; c < C2N; c += 256) {
        float acc = 0.f;
        #pragma unroll
        for (int h = 0; h < H2N; h++)
            acc += __ldg(&glp[h * C2N + c]) * w[h];
        atomicAdd(&op[c], acc);
    }
}

// ---------------- host ------------------------------------------------------
extern "C" void kernel_launch(void* const* d_in, const int* in_sizes, int n_in,
                              void* d_out, int out_size) {
    const float* x     = (const float*)d_in[0];
    const void*  ei    = d_in[1];               // dtype detected on device
    const float* Wq    = (const float*)d_in[2];
    const float* bq    = (const float*)d_in[3];
    const float* Wk    = (const float*)d_in[4];
    const float* bk    = (const float*)d_in[5];
    const float* Wv    = (const float*)d_in[6];
    const float* bv    = (const float*)d_in[7];
    const float* Wsk   = (const float*)d_in[8];
    const float* bsk   = (const float*)d_in[9];
    const float* Wl    = (const float*)d_in[10];
    const float* bl    = (const float*)d_in[11];
    const float* Wr    = (const float*)d_in[12];
    const float* br    = (const float*)d_in[13];
    const float* att   = (const float*)d_in[14];
    const float* b_out = (const float*)d_in[15];
    float*       out   = (float*)d_out;

    static float *pQ = nullptr, *pK = nullptr, *pV = nullptr,
                 *pH = nullptr, *pGL = nullptr, *pGR = nullptr;
    if (!pQ) {
        void* p;
        cudaGetSymbolAddress(&p, g_Q);  pQ  = (float*)p;
        cudaGetSymbolAddress(&p, g_K);  pK  = (float*)p;
        cudaGetSymbolAddress(&p, g_V);  pV  = (float*)p;
        cudaGetSymbolAddress(&p, g_H);  pH  = (float*)p;
        cudaGetSymbolAddress(&p, g_GL); pGL = (float*)p;
        cudaGetSymbolAddress(&p, g_GR); pGR = (float*)p;
    }

    // edge-index dtype detection + unpack
    detect_idx_kernel<<<1, 1>>>((const int*)ei);
    unpack_idx_kernel<<<(EE + 255) / 256, 256>>>(ei);

    // reset softmax stats + output
    init_stats_kernel<<<(NN * H2N + 255) / 256, 256>>>();
    out_init_kernel<<<(NN * C2N + 255) / 256, 256>>>(b_out, out);

    // layer-1 projections: M=10000, K=1024, N=2048 (tf32 tensor cores)
    dim3 g1(D1N / 128, (NN + 127) / 128);
    sgemm_tf32<<<g1, 256>>>(NN, D1N, INDIM, x, Wq,  bq,  pQ);
    sgemm_tf32<<<g1, 256>>>(NN, D1N, INDIM, x, Wk,  bk,  pK);
    sgemm_tf32<<<g1, 256>>>(NN, D1N, INDIM, x, Wv,  bv,  pV);
    sgemm_tf32<<<g1, 256>>>(NN, D1N, INDIM, x, Wsk, bsk, pH);

    // layer-1 attention + aggregation
    edge_alpha1_kernel<<<EE, H1N * 32>>>();
    exp1_kernel<<<(EE * H1N + 255) / 256, 256>>>();
    agg1_kernel<<<EE, 256>>>();
    elu_kernel<<<((NN * D1N) / 4 + 255) / 256, 256>>>();

    // layer-2 projections: M=10000, K=2048, N=3680
    dim3 g2((D2N + 127) / 128, (NN + 127) / 128);
    sgemm_tf32<<<g2, 256>>>(NN, D2N, D1N, pH, Wl, bl, pGL);
    sgemm_tf32<<<g2, 256>>>(NN, D2N, D1N, pH, Wr, br, pGR);

    // layer-2 attention + output
    edge_a2_kernel<<<E2N, H2N * 32>>>(att);
    exp2_kernel<<<(E2N * H2N + 255) / 256, 256>>>();
    out_acc_kernel<<<E2N, 256>>>(out);
}